// round 1
// baseline (speedup 1.0000x reference)
#include <cuda_runtime.h>
#include <cuda_bf16.h>
#include <math.h>

// Problem dims
#define BB 4096
#define TT 64
#define FF 256
#define HH 256
#define AA 12
#define MTOT (BB*TT)            // 262144 rows
#define G3  (3*HH)              // 768

// Scratch (device globals; no cudaMalloc allowed)
__device__ float g_xg [(size_t)MTOT * G3];   // input-side gates, [B*T, 768]
__device__ float g_lat[(size_t)MTOT * HH];   // GRU latent       [B*T, 256]
__device__ float g_t1 [(size_t)MTOT * HH];
__device__ float g_t2a[(size_t)MTOT * HH];
__device__ float g_t2c[(size_t)MTOT * HH];

// ---------------------------------------------------------------------------
// Generic SGEMM: C[M,N] = act(A[M,K] @ W[N,K]^T + bias[N])
// BM=128, BN=64, BK=16, 256 threads, 8x4 microtile.
// Requires M%128==0, N%64==0, K%16==0 (true here: K=256, N in {768,256}).
// ---------------------------------------------------------------------------
template<bool DO_TANH>
__global__ __launch_bounds__(256) void gemm_bias_kernel(
    const float* __restrict__ A, const float* __restrict__ W,
    const float* __restrict__ bias, float* __restrict__ C,
    int N, int K)
{
    __shared__ float As[16][129];
    __shared__ float Ws[16][65];

    const int bm = blockIdx.x * 128;
    const int bn = blockIdx.y * 64;
    const int tid = threadIdx.x;
    const int tx = tid & 15;        // column group: cols bn + tx + 16*j
    const int ty = tid >> 4;        // row group:   rows bm + ty*8 + i

    // load mappings
    const int arow = tid >> 1;            // 0..127
    const int ak   = (tid & 1) * 8;       // 0 or 8
    const int wrow = tid >> 2;            // 0..63
    const int wk   = (tid & 3) * 4;       // 0,4,8,12

    float acc[8][4];
#pragma unroll
    for (int i = 0; i < 8; i++)
#pragma unroll
        for (int j = 0; j < 4; j++) acc[i][j] = 0.f;

    const size_t a_base = (size_t)(bm + arow) * K;
    const size_t w_base = (size_t)(bn + wrow) * K;

    for (int k0 = 0; k0 < K; k0 += 16) {
        float4 a0 = *(const float4*)&A[a_base + k0 + ak];
        float4 a1 = *(const float4*)&A[a_base + k0 + ak + 4];
        float4 w0 = *(const float4*)&W[w_base + k0 + wk];
        As[ak+0][arow] = a0.x; As[ak+1][arow] = a0.y;
        As[ak+2][arow] = a0.z; As[ak+3][arow] = a0.w;
        As[ak+4][arow] = a1.x; As[ak+5][arow] = a1.y;
        As[ak+6][arow] = a1.z; As[ak+7][arow] = a1.w;
        Ws[wk+0][wrow] = w0.x; Ws[wk+1][wrow] = w0.y;
        Ws[wk+2][wrow] = w0.z; Ws[wk+3][wrow] = w0.w;
        __syncthreads();

#pragma unroll
        for (int k = 0; k < 16; k++) {
            float av[8], bv[4];
#pragma unroll
            for (int i = 0; i < 8; i++) av[i] = As[k][ty*8 + i];
#pragma unroll
            for (int j = 0; j < 4; j++) bv[j] = Ws[k][tx + 16*j];
#pragma unroll
            for (int i = 0; i < 8; i++)
#pragma unroll
                for (int j = 0; j < 4; j++)
                    acc[i][j] = fmaf(av[i], bv[j], acc[i][j]);
        }
        __syncthreads();
    }

    float bv[4];
#pragma unroll
    for (int j = 0; j < 4; j++) bv[j] = bias[bn + tx + 16*j];

#pragma unroll
    for (int i = 0; i < 8; i++) {
        size_t crow = (size_t)(bm + ty*8 + i) * N;
#pragma unroll
        for (int j = 0; j < 4; j++) {
            float v = acc[i][j] + bv[j];
            if (DO_TANH) v = tanhf(v);
            C[crow + bn + tx + 16*j] = v;
        }
    }
}

// ---------------------------------------------------------------------------
// GRU scan. Each block owns RB=16 batch rows for all T=64 steps.
// h lives in smem; W_hh streamed from L2 (resident: 786KB << 126MB L2).
// Per step: hg[16][768] = h @ W_hh^T via smem-tiled fp32 GEMM (3 parts of 256
// gates, K-tiles of 16), then pointwise GRU update fully in registers.
// Thread (tx=tid%64, ty=tid/64) owns rows ty*4+i, cols tx+64*j.
// ---------------------------------------------------------------------------
#define RB 16
__global__ __launch_bounds__(256) void gru_kernel(
    const float* __restrict__ xg,      // [B*T, 768] (includes b_ih)
    const float* __restrict__ h0,      // [B, 256]
    const float* __restrict__ W_hh,    // [768, 256]
    const float* __restrict__ b_hh,    // [768]
    const int*   __restrict__ starts,  // [B, T]
    float* __restrict__ lat,           // [B*T, 256]
    float* __restrict__ h_out)         // [B, 256]
{
    __shared__ float h_s[RB][257];
    __shared__ float w_s[16][257];
    __shared__ float smask[RB];

    const int b0  = blockIdx.x * RB;
    const int tid = threadIdx.x;
    const int tx  = tid & 63;
    const int ty  = tid >> 6;      // 0..3
    const int lk  = tid & 15;      // k lane within W-tile load
    const int g0  = tid >> 4;      // gate base within W-tile load

    // init h from h0
    for (int i = tid; i < RB*256; i += 256) {
        int r = i >> 8, c = i & 255;
        h_s[r][c] = h0[(size_t)(b0 + r) * 256 + c];
    }

    // per-thread recurrent biases for owned columns
    float bh[3][4];
#pragma unroll
    for (int j = 0; j < 4; j++) {
        int c = tx + 64*j;
        bh[0][j] = b_hh[c];
        bh[1][j] = b_hh[256 + c];
        bh[2][j] = b_hh[512 + c];
    }
    __syncthreads();

    for (int t = 0; t < TT; t++) {
        // episode reset mask
        if (tid < RB) smask[tid] = starts[(size_t)(b0 + tid) * TT + t] ? 0.f : 1.f;
        __syncthreads();
        for (int i = tid; i < RB*256; i += 256) {
            int r = i >> 8, c = i & 255;
            h_s[r][c] *= smask[r];
        }
        __syncthreads();

        float acc[3][4][4];
#pragma unroll
        for (int p = 0; p < 3; p++)
#pragma unroll
            for (int i = 0; i < 4; i++)
#pragma unroll
                for (int j = 0; j < 4; j++) acc[p][i][j] = 0.f;

#pragma unroll 1
        for (int part = 0; part < 3; part++) {
            for (int kk = 0; kk < 256; kk += 16) {
                // load W tile [16 k][256 gates], transposed to k-major
#pragma unroll
                for (int p = 0; p < 16; p++) {
                    int g = g0 + 16*p;
                    w_s[lk][g] = W_hh[(size_t)(part*256 + g) * 256 + kk + lk];
                }
                __syncthreads();
#pragma unroll
                for (int k = 0; k < 16; k++) {
                    float hv[4], wv[4];
#pragma unroll
                    for (int i = 0; i < 4; i++) hv[i] = h_s[ty*4 + i][kk + k];
#pragma unroll
                    for (int j = 0; j < 4; j++) wv[j] = w_s[k][tx + 64*j];
#pragma unroll
                    for (int i = 0; i < 4; i++)
#pragma unroll
                        for (int j = 0; j < 4; j++)
                            acc[part][i][j] = fmaf(hv[i], wv[j], acc[part][i][j]);
                }
                __syncthreads();
            }
        }

        // pointwise GRU update (each (row,col) owned by exactly one thread)
#pragma unroll
        for (int i = 0; i < 4; i++) {
            const int b = b0 + ty*4 + i;
            const size_t xbase = ((size_t)b * TT + t) * G3;
            const size_t lbase = ((size_t)b * TT + t) * 256;
#pragma unroll
            for (int j = 0; j < 4; j++) {
                const int c = tx + 64*j;
                float xr = xg[xbase + c];
                float xz = xg[xbase + 256 + c];
                float xn = xg[xbase + 512 + c];
                float hr = acc[0][i][j] + bh[0][j];
                float hz = acc[1][i][j] + bh[1][j];
                float hn = acc[2][i][j] + bh[2][j];
                float r = 1.f / (1.f + __expf(-(xr + hr)));
                float z = 1.f / (1.f + __expf(-(xz + hz)));
                float n = tanhf(xn + r * hn);
                float hold = h_s[ty*4 + i][c];
                float hnew = (1.f - z) * n + z * hold;
                h_s[ty*4 + i][c] = hnew;
                lat[lbase + c] = hnew;
            }
        }
        __syncthreads();
    }

    // final hidden state
    for (int i = tid; i < RB*256; i += 256) {
        int r = i >> 8, c = i & 255;
        h_out[(size_t)(b0 + r) * 256 + c] = h_s[r][c];
    }
}

// ---------------------------------------------------------------------------
// Heads: mean = t2a @ Aw3^T + Ab3 (12 cols), value = t2c . Cw3 + Cb3 (1 col)
// -> interleaved into out[m*13 + {0..12}]. One warp per row.
// ---------------------------------------------------------------------------
__global__ __launch_bounds__(256) void head_kernel(
    const float* __restrict__ t2a, const float* __restrict__ t2c,
    const float* __restrict__ Aw3, const float* __restrict__ Ab3,
    const float* __restrict__ Cw3, const float* __restrict__ Cb3,
    float* __restrict__ out)
{
    __shared__ float wa[12][256];
    __shared__ float wc[256];
    __shared__ float ba[12];
    __shared__ float bc;

    const int tid = threadIdx.x;
    for (int i = tid; i < 12*256; i += 256) wa[i >> 8][i & 255] = Aw3[i];
    if (tid < 256) wc[tid] = Cw3[tid];
    if (tid < 12)  ba[tid] = Ab3[tid];
    if (tid == 0)  bc = Cb3[0];
    __syncthreads();

    const int warp = tid >> 5;
    const int lane = tid & 31;
    const size_t row = (size_t)blockIdx.x * 8 + warp;

    const float* ra = t2a + row * 256;
    const float* rc = t2c + row * 256;
    float va[8], vc[8];
#pragma unroll
    for (int u = 0; u < 8; u++) {
        va[u] = ra[lane + 32*u];
        vc[u] = rc[lane + 32*u];
    }

    float s[13];
#pragma unroll
    for (int a = 0; a < 12; a++) {
        float acc = 0.f;
#pragma unroll
        for (int u = 0; u < 8; u++) acc = fmaf(va[u], wa[a][lane + 32*u], acc);
        s[a] = acc;
    }
    {
        float acc = 0.f;
#pragma unroll
        for (int u = 0; u < 8; u++) acc = fmaf(vc[u], wc[lane + 32*u], acc);
        s[12] = acc;
    }
#pragma unroll
    for (int a = 0; a < 13; a++) {
#pragma unroll
        for (int o = 16; o > 0; o >>= 1)
            s[a] += __shfl_xor_sync(0xffffffffu, s[a], o);
    }
    if (lane == 0) {
        float* o = out + row * 13;
#pragma unroll
        for (int a = 0; a < 12; a++) o[a] = s[a] + ba[a];
        o[12] = s[12] + bc;
    }
}

__global__ void std_kernel(const float* __restrict__ log_std, float* __restrict__ out)
{
    int a = threadIdx.x;
    if (a < AA) {
        float v = log_std[a];
        v = fminf(fmaxf(v, -2.0f), -0.5f);
        out[a] = __expf(v);
    }
}

// ---------------------------------------------------------------------------
extern "C" void kernel_launch(void* const* d_in, const int* in_sizes, int n_in,
                              void* d_out, int out_size)
{
    const float* features = (const float*)d_in[0];
    const float* hidden   = (const float*)d_in[1];
    const float* W_ih     = (const float*)d_in[2];
    const float* W_hh     = (const float*)d_in[3];
    const float* b_ih     = (const float*)d_in[4];
    const float* b_hh     = (const float*)d_in[5];
    const float* Aw1      = (const float*)d_in[6];
    const float* Ab1      = (const float*)d_in[7];
    const float* Aw2      = (const float*)d_in[8];
    const float* Ab2      = (const float*)d_in[9];
    const float* Aw3      = (const float*)d_in[10];
    const float* Ab3      = (const float*)d_in[11];
    const float* Cw1      = (const float*)d_in[12];
    const float* Cb1      = (const float*)d_in[13];
    const float* Cw2      = (const float*)d_in[14];
    const float* Cb2      = (const float*)d_in[15];
    const float* Cw3      = (const float*)d_in[16];
    const float* Cb3      = (const float*)d_in[17];
    const float* log_std  = (const float*)d_in[18];
    const int*   starts   = (const int*)d_in[19];

    float* out      = (float*)d_out;
    float* out_main = out;                          // [B*T, 13]
    float* out_std  = out + (size_t)MTOT * 13;      // [12]
    float* out_h    = out + (size_t)MTOT * 13 + AA; // [B, 256]

    float *xg, *lat, *t1, *t2a, *t2c;
    cudaGetSymbolAddress((void**)&xg,  g_xg);
    cudaGetSymbolAddress((void**)&lat, g_lat);
    cudaGetSymbolAddress((void**)&t1,  g_t1);
    cudaGetSymbolAddress((void**)&t2a, g_t2a);
    cudaGetSymbolAddress((void**)&t2c, g_t2c);

    dim3 blk(256);

    // 1) xg = features @ W_ih^T + b_ih        [262144, 768]
    gemm_bias_kernel<false><<<dim3(MTOT/128, G3/64), blk>>>(features, W_ih, b_ih, xg, G3, FF);

    // 2) GRU scan -> lat, h_last
    gru_kernel<<<BB/RB, blk>>>(xg, hidden, W_hh, b_hh, starts, lat, out_h);

    // 3) actor MLP
    gemm_bias_kernel<true><<<dim3(MTOT/128, HH/64), blk>>>(lat, Aw1, Ab1, t1,  HH, HH);
    gemm_bias_kernel<true><<<dim3(MTOT/128, HH/64), blk>>>(t1,  Aw2, Ab2, t2a, HH, HH);

    // 4) critic MLP
    gemm_bias_kernel<true><<<dim3(MTOT/128, HH/64), blk>>>(lat, Cw1, Cb1, t1,  HH, HH);
    gemm_bias_kernel<true><<<dim3(MTOT/128, HH/64), blk>>>(t1,  Cw2, Cb2, t2c, HH, HH);

    // 5) heads -> out[:, 0:13]
    head_kernel<<<MTOT/8, blk>>>(t2a, t2c, Aw3, Ab3, Cw3, Cb3, out_main);

    // 6) std
    std_kernel<<<1, 32>>>(log_std, out_std);
}

// round 3
// speedup vs baseline: 2.8901x; 2.8901x over previous
#include <cuda_runtime.h>
#include <math.h>
#include <stdint.h>

// Problem dims
#define BB 4096
#define TT 64
#define FF 256
#define HH 256
#define AA 12
#define MTOT (BB*TT)            // 262144 rows
#define G3  768

// Scratch (device globals; no cudaMalloc allowed)
__device__ float g_xg [(size_t)MTOT * G3];
__device__ float g_lat[(size_t)MTOT * HH];
__device__ float g_t1 [(size_t)MTOT * HH];
__device__ float g_t2a[(size_t)MTOT * HH];
__device__ float g_t2c[(size_t)MTOT * HH];
__device__ float g_wt [256 * 768];           // W_hh^T, tf32-rounded: [k][gate]

__device__ __forceinline__ float round_tf32(float x) {
    uint32_t r;
    asm("cvt.rna.tf32.f32 %0, %1;" : "=r"(r) : "f"(x));
    return __uint_as_float(r);
}

__device__ __forceinline__ void mma_tf32(
    float& c0, float& c1, float& c2, float& c3,
    uint32_t a0, uint32_t a1, uint32_t a2, uint32_t a3,
    uint32_t b0, uint32_t b1)
{
    asm volatile(
        "mma.sync.aligned.m16n8k8.row.col.f32.tf32.tf32.f32 "
        "{%0,%1,%2,%3}, {%4,%5,%6,%7}, {%8,%9}, {%0,%1,%2,%3};"
        : "+f"(c0), "+f"(c1), "+f"(c2), "+f"(c3)
        : "r"(a0), "r"(a1), "r"(a2), "r"(a3), "r"(b0), "r"(b1));
}

// ===========================================================================
// Prep: Wt[k][g] = round_tf32(W_hh[g][k])
// ===========================================================================
__global__ void prep_whh(const float* __restrict__ W_hh, float* __restrict__ Wt)
{
    int idx = blockIdx.x * 256 + threadIdx.x;       // over 768*256
    int g = idx >> 8, k = idx & 255;
    Wt[(size_t)k * 768 + g] = round_tf32(W_hh[(size_t)g * 256 + k]);
}

// ===========================================================================
// tf32 mma.sync GEMM: C[M,N] = act(A[M,K] @ W[N,K]^T + bias[N])
// 128x128x32 tile, 256 threads (8 warps, 2x4), warp tile 64x32.
// ===========================================================================
#define GBM 128
#define GBN 128
#define GBK 32
#define APITCH 36
#define STAGEF (GBM * APITCH)    // 4608 floats per A (or B) stage
// dyn smem: A[2][STAGEF] | B[2][STAGEF] | bias[GBN]
#define GEMM_SMEM ((4 * STAGEF + GBN) * 4)   // 74240 bytes

template<bool DO_TANH>
__global__ __launch_bounds__(256) void gemm_mma(
    const float* __restrict__ A, const float* __restrict__ W,
    const float* __restrict__ bias, float* __restrict__ C,
    int N, int K)
{
    extern __shared__ float sm[];
    float* sA    = sm;
    float* sB    = sm + 2 * STAGEF;
    float* sBias = sm + 4 * STAGEF;

    const int tid  = threadIdx.x;
    const int lane = tid & 31;
    const int wid  = tid >> 5;
    const int wm   = wid >> 2;         // 0..1
    const int wn   = wid & 3;          // 0..3
    const size_t bm = (size_t)blockIdx.x * GBM;
    const int    bn = blockIdx.y * GBN;

    if (tid < GBN) sBias[tid] = bias[bn + tid];

    const int lrow = tid >> 1;             // 0..127
    const int lkq  = (tid & 1) * 16;       // 0/16
    const float* Ag = A + (bm + lrow) * K + lkq;
    const float* Wg = W + ((size_t)(bn + lrow)) * K + lkq;

    float acc[4][4][4];
#pragma unroll
    for (int mt = 0; mt < 4; mt++)
#pragma unroll
        for (int nt = 0; nt < 4; nt++)
#pragma unroll
            for (int q = 0; q < 4; q++) acc[mt][nt][q] = 0.f;

    const int NK = K / GBK;

    // initial tile
    {
        float* dA = sA + lrow * APITCH + lkq;
        float* dB = sB + lrow * APITCH + lkq;
#pragma unroll
        for (int u = 0; u < 4; u++) {
            float4 v = *(const float4*)(Ag + 4 * u);
            v.x = round_tf32(v.x); v.y = round_tf32(v.y);
            v.z = round_tf32(v.z); v.w = round_tf32(v.w);
            *(float4*)(dA + 4 * u) = v;
            float4 wv = *(const float4*)(Wg + 4 * u);
            wv.x = round_tf32(wv.x); wv.y = round_tf32(wv.y);
            wv.z = round_tf32(wv.z); wv.w = round_tf32(wv.w);
            *(float4*)(dB + 4 * u) = wv;
        }
    }
    __syncthreads();

    for (int kt = 0; kt < NK; kt++) {
        const int buf = kt & 1;
        if (kt + 1 < NK) {
            const float* ap = Ag + (kt + 1) * GBK;
            const float* wp = Wg + (kt + 1) * GBK;
            float* dA = sA + (buf ^ 1) * STAGEF + lrow * APITCH + lkq;
            float* dB = sB + (buf ^ 1) * STAGEF + lrow * APITCH + lkq;
#pragma unroll
            for (int u = 0; u < 4; u++) {
                float4 v = *(const float4*)(ap + 4 * u);
                v.x = round_tf32(v.x); v.y = round_tf32(v.y);
                v.z = round_tf32(v.z); v.w = round_tf32(v.w);
                *(float4*)(dA + 4 * u) = v;
                float4 wv = *(const float4*)(wp + 4 * u);
                wv.x = round_tf32(wv.x); wv.y = round_tf32(wv.y);
                wv.z = round_tf32(wv.z); wv.w = round_tf32(wv.w);
                *(float4*)(dB + 4 * u) = wv;
            }
        }

        const float* bA = sA + buf * STAGEF;
        const float* bB = sB + buf * STAGEF;
#pragma unroll
        for (int k8 = 0; k8 < 4; k8++) {
            const int k0 = k8 * 8;
            uint32_t a[4][4];
#pragma unroll
            for (int mt = 0; mt < 4; mt++) {
                const float* p = bA + (wm * 64 + mt * 16 + (lane >> 2)) * APITCH
                               + k0 + (lane & 3);
                a[mt][0] = __float_as_uint(p[0]);
                a[mt][1] = __float_as_uint(p[8 * APITCH]);
                a[mt][2] = __float_as_uint(p[4]);
                a[mt][3] = __float_as_uint(p[8 * APITCH + 4]);
            }
            uint32_t b[4][2];
#pragma unroll
            for (int nt = 0; nt < 4; nt++) {
                const float* p = bB + (wn * 32 + nt * 8 + (lane >> 2)) * APITCH
                               + k0 + (lane & 3);
                b[nt][0] = __float_as_uint(p[0]);
                b[nt][1] = __float_as_uint(p[4]);
            }
#pragma unroll
            for (int mt = 0; mt < 4; mt++)
#pragma unroll
                for (int nt = 0; nt < 4; nt++)
                    mma_tf32(acc[mt][nt][0], acc[mt][nt][1],
                             acc[mt][nt][2], acc[mt][nt][3],
                             a[mt][0], a[mt][1], a[mt][2], a[mt][3],
                             b[nt][0], b[nt][1]);
        }
        __syncthreads();
    }

    // epilogue
#pragma unroll
    for (int mt = 0; mt < 4; mt++) {
        const size_t row = bm + wm * 64 + mt * 16 + (lane >> 2);
        float* c0p = C + row * N + bn + wn * 32;
        float* c1p = c0p + (size_t)8 * N;
#pragma unroll
        for (int nt = 0; nt < 4; nt++) {
            const int cc = nt * 8 + (lane & 3) * 2;
            const float bx = sBias[wn * 32 + cc];
            const float by = sBias[wn * 32 + cc + 1];
            float v0 = acc[mt][nt][0] + bx, v1 = acc[mt][nt][1] + by;
            float v2 = acc[mt][nt][2] + bx, v3 = acc[mt][nt][3] + by;
            if (DO_TANH) {
                v0 = tanhf(v0); v1 = tanhf(v1);
                v2 = tanhf(v2); v3 = tanhf(v3);
            }
            *(float2*)(c0p + cc) = make_float2(v0, v1);
            *(float2*)(c1p + cc) = make_float2(v2, v3);
        }
    }
}

// ===========================================================================
// GRU scan with mma.sync tf32. RB=32 batch rows/block, 128 blocks, 256 thr.
// Warp w owns hidden cols [32w,32w+32) in ALL 3 gate blocks -> pointwise in
// registers. h kept in fp32 (exact); only mma inputs rounded to tf32.
// ===========================================================================
#define RB2 32
#define HF_PITCH 257
#define HT_PITCH 260
#define WS_PITCH 776
#define WS_STAGE (16 * WS_PITCH)
// smem: hf[32][257] | ht[32][260] | ws[2][16][776] | sst[32][64] int | sbh[768]
#define GRU_SMEM ((32*HF_PITCH + 32*HT_PITCH + 2*WS_STAGE + 768) * 4 + 32*64*4)

__global__ __launch_bounds__(256, 1) void gru_mma(
    const float* __restrict__ xg, const float* __restrict__ h0,
    const float* __restrict__ Wt, const float* __restrict__ b_hh,
    const int* __restrict__ starts,
    float* __restrict__ lat, float* __restrict__ h_out)
{
    extern __shared__ float sm[];
    float* hf  = sm;                          // [32][257]
    float* ht  = hf + 32 * HF_PITCH;          // [32][260]
    float* ws  = ht + 32 * HT_PITCH;          // [2][16][776]
    int*   sst = (int*)(ws + 2 * WS_STAGE);   // [32][64]
    float* sbh = (float*)(sst + 32 * 64);     // [768]

    const int tid  = threadIdx.x;
    const int lane = tid & 31;
    const int w    = tid >> 5;
    const int b0   = blockIdx.x * RB2;

    for (int i = tid; i < 32 * 64; i += 256)
        sst[i] = starts[(size_t)(b0 + (i >> 6)) * TT + (i & 63)];
    for (int i = tid; i < 768; i += 256) sbh[i] = b_hh[i];
    for (int i = tid; i < 32 * 256; i += 256) {
        int r = i >> 8, c = i & 255;
        float v = h0[(size_t)(b0 + r) * 256 + c];
        if (starts[(size_t)(b0 + r) * TT]) v = 0.f;
        hf[r * HF_PITCH + c] = v;
        ht[r * HT_PITCH + c] = round_tf32(v);
    }

    // W staging mapping
    const int krow = tid >> 4;        // 0..15
    const int c4   = (tid & 15) * 4;  // float col base

    for (int t = 0; t < TT; t++) {
        // tile 0
        {
            const float* src = Wt + (size_t)krow * 768 + c4;
            float* dst = ws + krow * WS_PITCH + c4;
#pragma unroll
            for (int u = 0; u < 12; u++)
                *(float4*)(dst + u * 64) = *(const float4*)(src + u * 64);
        }
        __syncthreads();

        float acc[2][12][4];
#pragma unroll
        for (int mt = 0; mt < 2; mt++)
#pragma unroll
            for (int j = 0; j < 12; j++)
#pragma unroll
                for (int q = 0; q < 4; q++) acc[mt][j][q] = 0.f;

        for (int kt = 0; kt < 16; kt++) {
            const int buf = kt & 1;
            if (kt + 1 < 16) {
                const float* src = Wt + (size_t)((kt + 1) * 16 + krow) * 768 + c4;
                float* dst = ws + (buf ^ 1) * WS_STAGE + krow * WS_PITCH + c4;
#pragma unroll
                for (int u = 0; u < 12; u++)
                    *(float4*)(dst + u * 64) = *(const float4*)(src + u * 64);
            }
#pragma unroll
            for (int s = 0; s < 2; s++) {
                const int kg = kt * 16 + s * 8;
                uint32_t a[2][4];
#pragma unroll
                for (int mt = 0; mt < 2; mt++) {
                    const float* p = ht + (mt * 16 + (lane >> 2)) * HT_PITCH
                                   + kg + (lane & 3);
                    a[mt][0] = __float_as_uint(p[0]);
                    a[mt][1] = __float_as_uint(p[8 * HT_PITCH]);
                    a[mt][2] = __float_as_uint(p[4]);
                    a[mt][3] = __float_as_uint(p[8 * HT_PITCH + 4]);
                }
                const float* wb = ws + buf * WS_STAGE
                                + (s * 8 + (lane & 3)) * WS_PITCH;
#pragma unroll
                for (int g = 0; g < 3; g++)
#pragma unroll
                    for (int nt = 0; nt < 4; nt++) {
                        const int col = g * 256 + w * 32 + nt * 8 + (lane >> 2);
                        uint32_t bb0 = __float_as_uint(wb[col]);
                        uint32_t bb1 = __float_as_uint(wb[4 * WS_PITCH + col]);
                        const int j = g * 4 + nt;
                        mma_tf32(acc[0][j][0], acc[0][j][1], acc[0][j][2], acc[0][j][3],
                                 a[0][0], a[0][1], a[0][2], a[0][3], bb0, bb1);
                        mma_tf32(acc[1][j][0], acc[1][j][1], acc[1][j][2], acc[1][j][3],
                                 a[1][0], a[1][1], a[1][2], a[1][3], bb0, bb1);
                    }
            }
            __syncthreads();
        }

        // pointwise GRU update (register-resident gates)
#pragma unroll
        for (int mt = 0; mt < 2; mt++)
#pragma unroll
        for (int rh = 0; rh < 2; rh++) {
            const int row  = mt * 16 + rh * 8 + (lane >> 2);
            const int grow = b0 + row;
            const size_t gbt = (size_t)grow * TT + t;
            const float* xb = xg + gbt * 768;
            float* lb = lat + gbt * 256;
            float msk = 1.f;
            if (t < TT - 1) msk = sst[row * 64 + t + 1] ? 0.f : 1.f;
#pragma unroll
            for (int nt = 0; nt < 4; nt++) {
                const int c = w * 32 + nt * 8 + (lane & 3) * 2;
                float2 xr = *(const float2*)(xb + c);
                float2 xz = *(const float2*)(xb + 256 + c);
                float2 xn = *(const float2*)(xb + 512 + c);
                const int q = rh * 2;
                float hr0 = acc[mt][nt][q]     + sbh[c];
                float hr1 = acc[mt][nt][q + 1] + sbh[c + 1];
                float hz0 = acc[mt][4 + nt][q]     + sbh[256 + c];
                float hz1 = acc[mt][4 + nt][q + 1] + sbh[256 + c + 1];
                float hn0 = acc[mt][8 + nt][q]     + sbh[512 + c];
                float hn1 = acc[mt][8 + nt][q + 1] + sbh[512 + c + 1];
                float r0 = 1.f / (1.f + __expf(-(xr.x + hr0)));
                float r1 = 1.f / (1.f + __expf(-(xr.y + hr1)));
                float z0 = 1.f / (1.f + __expf(-(xz.x + hz0)));
                float z1 = 1.f / (1.f + __expf(-(xz.y + hz1)));
                float n0 = tanhf(xn.x + r0 * hn0);
                float n1 = tanhf(xn.y + r1 * hn1);
                float ho0 = hf[row * HF_PITCH + c];
                float ho1 = hf[row * HF_PITCH + c + 1];
                float v0 = (1.f - z0) * n0 + z0 * ho0;
                float v1 = (1.f - z1) * n1 + z1 * ho1;
                *(float2*)(lb + c) = make_float2(v0, v1);
                if (t == TT - 1) {
                    *(float2*)(h_out + (size_t)grow * 256 + c) = make_float2(v0, v1);
                } else {
                    float m0 = v0 * msk, m1 = v1 * msk;
                    hf[row * HF_PITCH + c]     = m0;
                    hf[row * HF_PITCH + c + 1] = m1;
                    ht[row * HT_PITCH + c]     = round_tf32(m0);
                    ht[row * HT_PITCH + c + 1] = round_tf32(m1);
                }
            }
        }
        // next iteration's tile-0 store + sync orders ht writes vs reads
    }
}

// ---------------------------------------------------------------------------
// Heads (unchanged)
// ---------------------------------------------------------------------------
__global__ __launch_bounds__(256) void head_kernel(
    const float* __restrict__ t2a, const float* __restrict__ t2c,
    const float* __restrict__ Aw3, const float* __restrict__ Ab3,
    const float* __restrict__ Cw3, const float* __restrict__ Cb3,
    float* __restrict__ out)
{
    __shared__ float wa[12][256];
    __shared__ float wc[256];
    __shared__ float ba[12];
    __shared__ float bc;

    const int tid = threadIdx.x;
    for (int i = tid; i < 12 * 256; i += 256) wa[i >> 8][i & 255] = Aw3[i];
    if (tid < 256) wc[tid] = Cw3[tid];
    if (tid < 12)  ba[tid] = Ab3[tid];
    if (tid == 0)  bc = Cb3[0];
    __syncthreads();

    const int warp = tid >> 5;
    const int lane = tid & 31;
    const size_t row = (size_t)blockIdx.x * 8 + warp;

    const float* ra = t2a + row * 256;
    const float* rc = t2c + row * 256;
    float va[8], vc[8];
#pragma unroll
    for (int u = 0; u < 8; u++) {
        va[u] = ra[lane + 32 * u];
        vc[u] = rc[lane + 32 * u];
    }

    float s[13];
#pragma unroll
    for (int a = 0; a < 12; a++) {
        float acc = 0.f;
#pragma unroll
        for (int u = 0; u < 8; u++) acc = fmaf(va[u], wa[a][lane + 32 * u], acc);
        s[a] = acc;
    }
    {
        float acc = 0.f;
#pragma unroll
        for (int u = 0; u < 8; u++) acc = fmaf(vc[u], wc[lane + 32 * u], acc);
        s[12] = acc;
    }
#pragma unroll
    for (int a = 0; a < 13; a++)
#pragma unroll
        for (int o = 16; o > 0; o >>= 1)
            s[a] += __shfl_xor_sync(0xffffffffu, s[a], o);
    if (lane == 0) {
        float* o = out + row * 13;
#pragma unroll
        for (int a = 0; a < 12; a++) o[a] = s[a] + ba[a];
        o[12] = s[12] + bc;
    }
}

__global__ void std_kernel(const float* __restrict__ log_std, float* __restrict__ out)
{
    int a = threadIdx.x;
    if (a < AA) {
        float v = log_std[a];
        v = fminf(fmaxf(v, -2.0f), -0.5f);
        out[a] = __expf(v);
    }
}

// ---------------------------------------------------------------------------
extern "C" void kernel_launch(void* const* d_in, const int* in_sizes, int n_in,
                              void* d_out, int out_size)
{
    const float* features = (const float*)d_in[0];
    const float* hidden   = (const float*)d_in[1];
    const float* W_ih     = (const float*)d_in[2];
    const float* W_hh     = (const float*)d_in[3];
    const float* b_ih     = (const float*)d_in[4];
    const float* b_hh     = (const float*)d_in[5];
    const float* Aw1      = (const float*)d_in[6];
    const float* Ab1      = (const float*)d_in[7];
    const float* Aw2      = (const float*)d_in[8];
    const float* Ab2      = (const float*)d_in[9];
    const float* Aw3      = (const float*)d_in[10];
    const float* Ab3      = (const float*)d_in[11];
    const float* Cw1      = (const float*)d_in[12];
    const float* Cb1      = (const float*)d_in[13];
    const float* Cw2      = (const float*)d_in[14];
    const float* Cb2      = (const float*)d_in[15];
    const float* Cw3      = (const float*)d_in[16];
    const float* Cb3      = (const float*)d_in[17];
    const float* log_std  = (const float*)d_in[18];
    const int*   starts   = (const int*)d_in[19];

    float* out      = (float*)d_out;
    float* out_main = out;
    float* out_std  = out + (size_t)MTOT * 13;
    float* out_h    = out + (size_t)MTOT * 13 + AA;

    float *xg, *lat, *t1, *t2a, *t2c, *wt;
    cudaGetSymbolAddress((void**)&xg,  g_xg);
    cudaGetSymbolAddress((void**)&lat, g_lat);
    cudaGetSymbolAddress((void**)&t1,  g_t1);
    cudaGetSymbolAddress((void**)&t2a, g_t2a);
    cudaGetSymbolAddress((void**)&t2c, g_t2c);
    cudaGetSymbolAddress((void**)&wt,  g_wt);

    cudaFuncSetAttribute(gemm_mma<false>,
                         cudaFuncAttributeMaxDynamicSharedMemorySize, GEMM_SMEM);
    cudaFuncSetAttribute(gemm_mma<true>,
                         cudaFuncAttributeMaxDynamicSharedMemorySize, GEMM_SMEM);
    cudaFuncSetAttribute(gru_mma,
                         cudaFuncAttributeMaxDynamicSharedMemorySize, GRU_SMEM);

    dim3 blk(256);

    // 0) prep W_hh -> transposed tf32 layout
    prep_whh<<<768, blk>>>(W_hh, wt);

    // 1) xg = features @ W_ih^T + b_ih        [262144, 768]
    gemm_mma<false><<<dim3(MTOT/GBM, G3/GBN), blk, GEMM_SMEM>>>(
        features, W_ih, b_ih, xg, G3, FF);

    // 2) GRU scan -> lat, h_last
    gru_mma<<<BB/RB2, blk, GRU_SMEM>>>(xg, hidden, wt, b_hh, starts, lat, out_h);

    // 3) actor MLP
    gemm_mma<true><<<dim3(MTOT/GBM, HH/GBN), blk, GEMM_SMEM>>>(lat, Aw1, Ab1, t1,  HH, HH);
    gemm_mma<true><<<dim3(MTOT/GBM, HH/GBN), blk, GEMM_SMEM>>>(t1,  Aw2, Ab2, t2a, HH, HH);

    // 4) critic MLP
    gemm_mma<true><<<dim3(MTOT/GBM, HH/GBN), blk, GEMM_SMEM>>>(lat, Cw1, Cb1, t1,  HH, HH);
    gemm_mma<true><<<dim3(MTOT/GBM, HH/GBN), blk, GEMM_SMEM>>>(t1,  Cw2, Cb2, t2c, HH, HH);

    // 5) heads -> out[:, 0:13]
    head_kernel<<<MTOT/8, blk>>>(t2a, t2c, Aw3, Ab3, Cw3, Cb3, out_main);

    // 6) std
    std_kernel<<<1, 32>>>(log_std, out_std);
}

// round 4
// speedup vs baseline: 3.1892x; 1.1035x over previous
#include <cuda_runtime.h>
#include <math.h>
#include <stdint.h>

// Problem dims
#define BB 4096
#define TT 64
#define FF 256
#define HH 256
#define AA 12
#define MTOT (BB*TT)            // 262144 rows
#define G3  768

// Scratch (device globals; no cudaMalloc allowed)
__device__ float g_xg [(size_t)MTOT * G3];     // xg, later reused as t12 [M,512]
__device__ float g_lat[(size_t)MTOT * HH];
__device__ float g_t1 [(size_t)MTOT * HH];     // rounded features
__device__ float g_t2a[(size_t)MTOT * HH];
__device__ float g_t2c[(size_t)MTOT * HH];
__device__ float g_wt  [256 * 768];            // W_hh^T rounded [k][gate]
__device__ float g_wihr[768 * 256];            // W_ih rounded
__device__ float g_w1c [512 * 256];            // [Aw1; Cw1] rounded
__device__ float g_w2a [256 * 256];
__device__ float g_w2c [256 * 256];
__device__ float g_b1c [512];                  // [Ab1 | Cb1]

__device__ __forceinline__ float round_tf32(float x) {
    uint32_t r;
    asm("cvt.rna.tf32.f32 %0, %1;" : "=r"(r) : "f"(x));
    return __uint_as_float(r);
}

__device__ __forceinline__ uint32_t smem_u32(const void* p) {
    uint32_t a;
    asm("{ .reg .u64 t; cvta.to.shared.u64 t, %1; cvt.u32.u64 %0, t; }"
        : "=r"(a) : "l"(p));
    return a;
}

__device__ __forceinline__ void cp16_cg(void* dst, const void* src) {
    asm volatile("cp.async.cg.shared.global [%0], [%1], 16;"
                 :: "r"(smem_u32(dst)), "l"(src) : "memory");
}
#define CP_COMMIT()  asm volatile("cp.async.commit_group;" ::: "memory")
#define CP_WAIT1()   asm volatile("cp.async.wait_group 1;" ::: "memory")
#define CP_WAITALL() asm volatile("cp.async.wait_all;" ::: "memory")

__device__ __forceinline__ void mma_tf32(
    float& c0, float& c1, float& c2, float& c3,
    uint32_t a0, uint32_t a1, uint32_t a2, uint32_t a3,
    uint32_t b0, uint32_t b1)
{
    asm volatile(
        "mma.sync.aligned.m16n8k8.row.col.f32.tf32.tf32.f32 "
        "{%0,%1,%2,%3}, {%4,%5,%6,%7}, {%8,%9}, {%0,%1,%2,%3};"
        : "+f"(c0), "+f"(c1), "+f"(c2), "+f"(c3)
        : "r"(a0), "r"(a1), "r"(a2), "r"(a3), "r"(b0), "r"(b1));
}

// ===========================================================================
// Prep kernels
// ===========================================================================
__global__ void prep_whh(const float* __restrict__ W_hh, float* __restrict__ Wt)
{
    int idx = blockIdx.x * 256 + threadIdx.x;
    int g = idx >> 8, k = idx & 255;
    Wt[(size_t)k * 768 + g] = round_tf32(W_hh[(size_t)g * 256 + k]);
}

__global__ void round_copy4(const float4* __restrict__ src, float4* __restrict__ dst)
{
    size_t i = (size_t)blockIdx.x * 256 + threadIdx.x;
    float4 v = src[i];
    v.x = round_tf32(v.x); v.y = round_tf32(v.y);
    v.z = round_tf32(v.z); v.w = round_tf32(v.w);
    dst[i] = v;
}

// ===========================================================================
// tf32 mma.sync GEMM with cp.async 3-stage pipeline.
// C[M,N] = act(A[M,K] @ W[N,K]^T + bias[N]); A,W pre-rounded tf32.
// Tile 128x128x32, 256 threads (2x4 warps), warp tile 64x32.
// grid = (N/128, M/128)  -- N-dim fastest for A reuse in L2.
// ===========================================================================
#define GBM 128
#define GBN 128
#define GBK 32
#define APITCH 36
#define STAGEF (GBM * APITCH)            // 4608 floats (A or B)
#define GEMM_SMEM ((6 * STAGEF + GBN) * 4)   // 3 stages * (A+B) + bias = 111104 B

template<bool DO_TANH, bool ROUND_OUT>
__global__ __launch_bounds__(256) void gemm_mma(
    const float* __restrict__ A, const float* __restrict__ W,
    const float* __restrict__ bias, float* __restrict__ C,
    int N, int K, int lda)
{
    extern __shared__ float sm[];
    float* sBias = sm + 6 * STAGEF;

    const int tid  = threadIdx.x;
    const int lane = tid & 31;
    const int wid  = tid >> 5;
    const int wm   = wid >> 2;         // 0..1
    const int wn   = wid & 3;          // 0..3
    const int    bn = blockIdx.x * GBN;
    const size_t bm = (size_t)blockIdx.y * GBM;

    if (tid < GBN) sBias[tid] = bias[bn + tid];

    const int lrow = tid >> 1;             // 0..127
    const int lkq  = (tid & 1) * 16;       // 0/16
    const float* Ag = A + (bm + lrow) * lda + lkq;
    const float* Wg = W + ((size_t)(bn + lrow)) * K + lkq;

    float acc[4][4][4];
#pragma unroll
    for (int mt = 0; mt < 4; mt++)
#pragma unroll
        for (int nt = 0; nt < 4; nt++)
#pragma unroll
            for (int q = 0; q < 4; q++) acc[mt][nt][q] = 0.f;

    const int NK = K / GBK;

    // stage copy: A tile rows 0..127 x 32 floats, B same
    auto stage_copy = [&](int kt) {
        float* st = sm + (kt % 3) * 2 * STAGEF;
        const float* ap = Ag + kt * GBK;
        const float* wp = Wg + kt * GBK;
        float* dA = st + lrow * APITCH + lkq;
        float* dB = st + STAGEF + lrow * APITCH + lkq;
#pragma unroll
        for (int u = 0; u < 4; u++) {
            cp16_cg(dA + 4 * u, ap + 4 * u);
            cp16_cg(dB + 4 * u, wp + 4 * u);
        }
    };

    stage_copy(0); CP_COMMIT();
    stage_copy(1); CP_COMMIT();

    for (int kt = 0; kt < NK; kt++) {
        if (kt == NK - 1) { CP_WAITALL(); } else { CP_WAIT1(); }
        __syncthreads();
        if (kt + 2 < NK) { stage_copy(kt + 2); CP_COMMIT(); }

        const float* bA = sm + (kt % 3) * 2 * STAGEF;
        const float* bB = bA + STAGEF;
#pragma unroll
        for (int k8 = 0; k8 < 4; k8++) {
            const int k0 = k8 * 8;
            uint32_t a[4][4];
#pragma unroll
            for (int mt = 0; mt < 4; mt++) {
                const float* p = bA + (wm * 64 + mt * 16 + (lane >> 2)) * APITCH
                               + k0 + (lane & 3);
                a[mt][0] = __float_as_uint(p[0]);
                a[mt][1] = __float_as_uint(p[8 * APITCH]);
                a[mt][2] = __float_as_uint(p[4]);
                a[mt][3] = __float_as_uint(p[8 * APITCH + 4]);
            }
            uint32_t b[4][2];
#pragma unroll
            for (int nt = 0; nt < 4; nt++) {
                const float* p = bB + (wn * 32 + nt * 8 + (lane >> 2)) * APITCH
                               + k0 + (lane & 3);
                b[nt][0] = __float_as_uint(p[0]);
                b[nt][1] = __float_as_uint(p[4]);
            }
#pragma unroll
            for (int mt = 0; mt < 4; mt++)
#pragma unroll
                for (int nt = 0; nt < 4; nt++)
                    mma_tf32(acc[mt][nt][0], acc[mt][nt][1],
                             acc[mt][nt][2], acc[mt][nt][3],
                             a[mt][0], a[mt][1], a[mt][2], a[mt][3],
                             b[nt][0], b[nt][1]);
        }
        __syncthreads();
    }

    // epilogue
#pragma unroll
    for (int mt = 0; mt < 4; mt++) {
        const size_t row = bm + wm * 64 + mt * 16 + (lane >> 2);
        float* c0p = C + row * N + bn + wn * 32;
        float* c1p = c0p + (size_t)8 * N;
#pragma unroll
        for (int nt = 0; nt < 4; nt++) {
            const int cc = nt * 8 + (lane & 3) * 2;
            const float bx = sBias[wn * 32 + cc];
            const float by = sBias[wn * 32 + cc + 1];
            float v0 = acc[mt][nt][0] + bx, v1 = acc[mt][nt][1] + by;
            float v2 = acc[mt][nt][2] + bx, v3 = acc[mt][nt][3] + by;
            if (DO_TANH) {
                v0 = tanhf(v0); v1 = tanhf(v1);
                v2 = tanhf(v2); v3 = tanhf(v3);
            }
            if (ROUND_OUT) {
                v0 = round_tf32(v0); v1 = round_tf32(v1);
                v2 = round_tf32(v2); v3 = round_tf32(v3);
            }
            *(float2*)(c0p + cc) = make_float2(v0, v1);
            *(float2*)(c1p + cc) = make_float2(v2, v3);
        }
    }
}

// ===========================================================================
// GRU scan with mma.sync tf32 + cp.async W streaming.
// RB=32 rows/block, 128 blocks, 256 threads. lat written tf32-rounded.
// ===========================================================================
#define RB2 32
#define HF_PITCH 257
#define HT_PITCH 260
#define WS_PITCH 776
#define WS_STAGE (16 * WS_PITCH)
#define GRU_SMEM ((32*HF_PITCH + 32*HT_PITCH + 2*WS_STAGE + 768) * 4 + 32*64*4)

__global__ __launch_bounds__(256, 1) void gru_mma(
    const float* __restrict__ xg, const float* __restrict__ h0,
    const float* __restrict__ Wt, const float* __restrict__ b_hh,
    const int* __restrict__ starts,
    float* __restrict__ lat, float* __restrict__ h_out)
{
    extern __shared__ float sm[];
    float* hf  = sm;                          // [32][257]
    float* ht  = hf + 32 * HF_PITCH;          // [32][260]
    float* ws  = ht + 32 * HT_PITCH;          // [2][16][776]
    int*   sst = (int*)(ws + 2 * WS_STAGE);   // [32][64]
    float* sbh = (float*)(sst + 32 * 64);     // [768]

    const int tid  = threadIdx.x;
    const int lane = tid & 31;
    const int w    = tid >> 5;
    const int b0   = blockIdx.x * RB2;

    for (int i = tid; i < 32 * 64; i += 256)
        sst[i] = starts[(size_t)(b0 + (i >> 6)) * TT + (i & 63)];
    for (int i = tid; i < 768; i += 256) sbh[i] = b_hh[i];
    for (int i = tid; i < 32 * 256; i += 256) {
        int r = i >> 8, c = i & 255;
        float v = h0[(size_t)(b0 + r) * 256 + c];
        if (starts[(size_t)(b0 + r) * TT]) v = 0.f;
        hf[r * HF_PITCH + c] = v;
        ht[r * HT_PITCH + c] = round_tf32(v);
    }

    const int krow = tid >> 4;        // 0..15
    const int c4   = (tid & 15) * 4;

    auto stageW = [&](int kt) {
        const float* src = Wt + (size_t)(kt * 16 + krow) * 768 + c4;
        float* dst = ws + (kt & 1) * WS_STAGE + krow * WS_PITCH + c4;
#pragma unroll
        for (int u = 0; u < 12; u++)
            cp16_cg(dst + u * 64, src + u * 64);
    };

    for (int t = 0; t < TT; t++) {
        stageW(0); CP_COMMIT();

        float acc[2][12][4];
#pragma unroll
        for (int mt = 0; mt < 2; mt++)
#pragma unroll
            for (int j = 0; j < 12; j++)
#pragma unroll
                for (int q = 0; q < 4; q++) acc[mt][j][q] = 0.f;

        for (int kt = 0; kt < 16; kt++) {
            const int buf = kt & 1;
            if (kt < 15) { stageW(kt + 1); CP_COMMIT(); CP_WAIT1(); }
            else         { CP_WAITALL(); }
            __syncthreads();   // W tile kt visible; (kt==0) also orders ht writes

#pragma unroll
            for (int s = 0; s < 2; s++) {
                const int kg = kt * 16 + s * 8;
                uint32_t a[2][4];
#pragma unroll
                for (int mt = 0; mt < 2; mt++) {
                    const float* p = ht + (mt * 16 + (lane >> 2)) * HT_PITCH
                                   + kg + (lane & 3);
                    a[mt][0] = __float_as_uint(p[0]);
                    a[mt][1] = __float_as_uint(p[8 * HT_PITCH]);
                    a[mt][2] = __float_as_uint(p[4]);
                    a[mt][3] = __float_as_uint(p[8 * HT_PITCH + 4]);
                }
                const float* wb = ws + buf * WS_STAGE
                                + (s * 8 + (lane & 3)) * WS_PITCH;
#pragma unroll
                for (int g = 0; g < 3; g++)
#pragma unroll
                    for (int nt = 0; nt < 4; nt++) {
                        const int col = g * 256 + w * 32 + nt * 8 + (lane >> 2);
                        uint32_t bb0 = __float_as_uint(wb[col]);
                        uint32_t bb1 = __float_as_uint(wb[4 * WS_PITCH + col]);
                        const int j = g * 4 + nt;
                        mma_tf32(acc[0][j][0], acc[0][j][1], acc[0][j][2], acc[0][j][3],
                                 a[0][0], a[0][1], a[0][2], a[0][3], bb0, bb1);
                        mma_tf32(acc[1][j][0], acc[1][j][1], acc[1][j][2], acc[1][j][3],
                                 a[1][0], a[1][1], a[1][2], a[1][3], bb0, bb1);
                    }
            }
            __syncthreads();   // done with buf before it's overwritten
        }

        // pointwise GRU update
#pragma unroll
        for (int mt = 0; mt < 2; mt++)
#pragma unroll
        for (int rh = 0; rh < 2; rh++) {
            const int row  = mt * 16 + rh * 8 + (lane >> 2);
            const int grow = b0 + row;
            const size_t gbt = (size_t)grow * TT + t;
            const float* xb = xg + gbt * 768;
            float* lb = lat + gbt * 256;
            float msk = 1.f;
            if (t < TT - 1) msk = sst[row * 64 + t + 1] ? 0.f : 1.f;
#pragma unroll
            for (int nt = 0; nt < 4; nt++) {
                const int c = w * 32 + nt * 8 + (lane & 3) * 2;
                float2 xr = *(const float2*)(xb + c);
                float2 xz = *(const float2*)(xb + 256 + c);
                float2 xn = *(const float2*)(xb + 512 + c);
                const int q = rh * 2;
                float hr0 = acc[mt][nt][q]     + sbh[c];
                float hr1 = acc[mt][nt][q + 1] + sbh[c + 1];
                float hz0 = acc[mt][4 + nt][q]     + sbh[256 + c];
                float hz1 = acc[mt][4 + nt][q + 1] + sbh[256 + c + 1];
                float hn0 = acc[mt][8 + nt][q]     + sbh[512 + c];
                float hn1 = acc[mt][8 + nt][q + 1] + sbh[512 + c + 1];
                float r0 = 1.f / (1.f + __expf(-(xr.x + hr0)));
                float r1 = 1.f / (1.f + __expf(-(xr.y + hr1)));
                float z0 = 1.f / (1.f + __expf(-(xz.x + hz0)));
                float z1 = 1.f / (1.f + __expf(-(xz.y + hz1)));
                float n0 = tanhf(xn.x + r0 * hn0);
                float n1 = tanhf(xn.y + r1 * hn1);
                float ho0 = hf[row * HF_PITCH + c];
                float ho1 = hf[row * HF_PITCH + c + 1];
                float v0 = (1.f - z0) * n0 + z0 * ho0;
                float v1 = (1.f - z1) * n1 + z1 * ho1;
                *(float2*)(lb + c) = make_float2(round_tf32(v0), round_tf32(v1));
                if (t == TT - 1) {
                    *(float2*)(h_out + (size_t)grow * 256 + c) = make_float2(v0, v1);
                } else {
                    float m0 = v0 * msk, m1 = v1 * msk;
                    hf[row * HF_PITCH + c]     = m0;
                    hf[row * HF_PITCH + c + 1] = m1;
                    ht[row * HT_PITCH + c]     = round_tf32(m0);
                    ht[row * HT_PITCH + c + 1] = round_tf32(m1);
                }
            }
        }
        // first barrier of next t's kt=0 orders ht writes vs mma reads
    }
}

// ---------------------------------------------------------------------------
// Heads
// ---------------------------------------------------------------------------
__global__ __launch_bounds__(256) void head_kernel(
    const float* __restrict__ t2a, const float* __restrict__ t2c,
    const float* __restrict__ Aw3, const float* __restrict__ Ab3,
    const float* __restrict__ Cw3, const float* __restrict__ Cb3,
    float* __restrict__ out)
{
    __shared__ float wa[12][256];
    __shared__ float wc[256];
    __shared__ float ba[12];
    __shared__ float bc;

    const int tid = threadIdx.x;
    for (int i = tid; i < 12 * 256; i += 256) wa[i >> 8][i & 255] = Aw3[i];
    if (tid < 256) wc[tid] = Cw3[tid];
    if (tid < 12)  ba[tid] = Ab3[tid];
    if (tid == 0)  bc = Cb3[0];
    __syncthreads();

    const int warp = tid >> 5;
    const int lane = tid & 31;
    const size_t row = (size_t)blockIdx.x * 8 + warp;

    const float* ra = t2a + row * 256;
    const float* rc = t2c + row * 256;
    float va[8], vc[8];
#pragma unroll
    for (int u = 0; u < 8; u++) {
        va[u] = ra[lane + 32 * u];
        vc[u] = rc[lane + 32 * u];
    }

    float s[13];
#pragma unroll
    for (int a = 0; a < 12; a++) {
        float acc = 0.f;
#pragma unroll
        for (int u = 0; u < 8; u++) acc = fmaf(va[u], wa[a][lane + 32 * u], acc);
        s[a] = acc;
    }
    {
        float acc = 0.f;
#pragma unroll
        for (int u = 0; u < 8; u++) acc = fmaf(vc[u], wc[lane + 32 * u], acc);
        s[12] = acc;
    }
#pragma unroll
    for (int a = 0; a < 13; a++)
#pragma unroll
        for (int o = 16; o > 0; o >>= 1)
            s[a] += __shfl_xor_sync(0xffffffffu, s[a], o);
    if (lane == 0) {
        float* o = out + row * 13;
#pragma unroll
        for (int a = 0; a < 12; a++) o[a] = s[a] + ba[a];
        o[12] = s[12] + bc;
    }
}

__global__ void std_kernel(const float* __restrict__ log_std, float* __restrict__ out)
{
    int a = threadIdx.x;
    if (a < AA) {
        float v = log_std[a];
        v = fminf(fmaxf(v, -2.0f), -0.5f);
        out[a] = __expf(v);
    }
}

// ---------------------------------------------------------------------------
extern "C" void kernel_launch(void* const* d_in, const int* in_sizes, int n_in,
                              void* d_out, int out_size)
{
    const float* features = (const float*)d_in[0];
    const float* hidden   = (const float*)d_in[1];
    const float* W_ih     = (const float*)d_in[2];
    const float* W_hh     = (const float*)d_in[3];
    const float* b_ih     = (const float*)d_in[4];
    const float* b_hh     = (const float*)d_in[5];
    const float* Aw1      = (const float*)d_in[6];
    const float* Ab1      = (const float*)d_in[7];
    const float* Aw2      = (const float*)d_in[8];
    const float* Ab2      = (const float*)d_in[9];
    const float* Aw3      = (const float*)d_in[10];
    const float* Ab3      = (const float*)d_in[11];
    const float* Cw1      = (const float*)d_in[12];
    const float* Cb1      = (const float*)d_in[13];
    const float* Cw2      = (const float*)d_in[14];
    const float* Cb2      = (const float*)d_in[15];
    const float* Cw3      = (const float*)d_in[16];
    const float* Cb3      = (const float*)d_in[17];
    const float* log_std  = (const float*)d_in[18];
    const int*   starts   = (const int*)d_in[19];

    float* out      = (float*)d_out;
    float* out_main = out;
    float* out_std  = out + (size_t)MTOT * 13;
    float* out_h    = out + (size_t)MTOT * 13 + AA;

    float *xg, *lat, *t1, *t2a, *t2c, *wt, *wihr, *w1c, *w2a, *w2c, *b1c;
    cudaGetSymbolAddress((void**)&xg,   g_xg);
    cudaGetSymbolAddress((void**)&lat,  g_lat);
    cudaGetSymbolAddress((void**)&t1,   g_t1);
    cudaGetSymbolAddress((void**)&t2a,  g_t2a);
    cudaGetSymbolAddress((void**)&t2c,  g_t2c);
    cudaGetSymbolAddress((void**)&wt,   g_wt);
    cudaGetSymbolAddress((void**)&wihr, g_wihr);
    cudaGetSymbolAddress((void**)&w1c,  g_w1c);
    cudaGetSymbolAddress((void**)&w2a,  g_w2a);
    cudaGetSymbolAddress((void**)&w2c,  g_w2c);
    cudaGetSymbolAddress((void**)&b1c,  g_b1c);

    cudaFuncSetAttribute(gemm_mma<false, false>,
                         cudaFuncAttributeMaxDynamicSharedMemorySize, GEMM_SMEM);
    cudaFuncSetAttribute(gemm_mma<true, true>,
                         cudaFuncAttributeMaxDynamicSharedMemorySize, GEMM_SMEM);
    cudaFuncSetAttribute(gemm_mma<true, false>,
                         cudaFuncAttributeMaxDynamicSharedMemorySize, GEMM_SMEM);
    cudaFuncSetAttribute(gru_mma,
                         cudaFuncAttributeMaxDynamicSharedMemorySize, GRU_SMEM);

    dim3 blk(256);

    // 0) prep: round weights + features, transpose W_hh, concat biases
    prep_whh<<<768, blk>>>(W_hh, wt);
    round_copy4<<<(768*256)/1024, blk>>>((const float4*)W_ih, (float4*)wihr);
    round_copy4<<<(256*256)/1024, blk>>>((const float4*)Aw1, (float4*)w1c);
    round_copy4<<<(256*256)/1024, blk>>>((const float4*)Cw1, (float4*)(w1c + 256*256));
    round_copy4<<<(256*256)/1024, blk>>>((const float4*)Aw2, (float4*)w2a);
    round_copy4<<<(256*256)/1024, blk>>>((const float4*)Cw2, (float4*)w2c);
    round_copy4<<<((size_t)MTOT*256)/1024, blk>>>((const float4*)features, (float4*)t1);
    cudaMemcpyAsync(b1c,       Ab1, 256 * 4, cudaMemcpyDeviceToDevice);
    cudaMemcpyAsync(b1c + 256, Cb1, 256 * 4, cudaMemcpyDeviceToDevice);

    // 1) xg = features @ W_ih^T + b_ih        [262144, 768]
    gemm_mma<false, false><<<dim3(G3/GBN, MTOT/GBM), blk, GEMM_SMEM>>>(
        t1, wihr, b_ih, xg, G3, FF, FF);

    // 2) GRU scan -> lat (tf32-rounded), h_last
    gru_mma<<<BB/RB2, blk, GRU_SMEM>>>(xg, hidden, wt, b_hh, starts, lat, out_h);

    // 3) fused actor+critic layer1: t12 = tanh(lat @ [Aw1;Cw1]^T + [Ab1|Cb1])
    //    (reuses g_xg as [M,512] scratch)
    gemm_mma<true, true><<<dim3(512/GBN, MTOT/GBM), blk, GEMM_SMEM>>>(
        lat, w1c, b1c, xg, 512, HH, HH);

    // 4) layer2 actor / critic (A = t12 slices, lda=512)
    gemm_mma<true, false><<<dim3(HH/GBN, MTOT/GBM), blk, GEMM_SMEM>>>(
        xg,        w2a, Ab2, t2a, HH, HH, 512);
    gemm_mma<true, false><<<dim3(HH/GBN, MTOT/GBM), blk, GEMM_SMEM>>>(
        xg + 256,  w2c, Cb2, t2c, HH, HH, 512);

    // 5) heads -> out[:, 0:13]
    head_kernel<<<MTOT/8, blk>>>(t2a, t2c, Aw3, Ab3, Cw3, Cb3, out_main);

    // 6) std
    std_kernel<<<1, 32>>>(log_std, out_std);
}